// round 1
// baseline (speedup 1.0000x reference)
#include <cuda_runtime.h>
#include <cuda_bf16.h>
#include <cstdint>

// Problem constants
#define BB 4
#define SS 2048
#define DD 1024
#define NH 4
#define DH 256
#define NSEQ (BB*NH)          // 16 independent (b,h) sequences
#define CLN 8                 // CTAs per cluster in scan

// ---------------------------------------------------------------------------
// Scratch (device globals — no runtime allocation allowed)
// ---------------------------------------------------------------------------
__device__ float d_xconv[(size_t)BB*SS*DD];                // 33.5 MB
__device__ float d_G[(size_t)BB*NH*SS*4*DH];               // 134 MB  gates+rec_bias, layout [cid][s][g*256+e]
__device__ float d_ys[(size_t)BB*NH*SS*DH];                // 33.5 MB raw y before groupnorm

// ---------------------------------------------------------------------------
// f32x2 helpers (FFMA2 — only reachable via PTX on sm_103a)
// ---------------------------------------------------------------------------
__device__ __forceinline__ unsigned long long pack2(float lo, float hi) {
    unsigned long long d;
    asm("mov.b64 %0, {%1,%2};" : "=l"(d) : "f"(lo), "f"(hi));
    return d;
}
__device__ __forceinline__ unsigned long long fma2(unsigned long long a,
                                                   unsigned long long b,
                                                   unsigned long long c) {
    unsigned long long d;
    asm("fma.rn.f32x2 %0, %1, %2, %3;" : "=l"(d) : "l"(a), "l"(b), "l"(c));
    return d;
}
__device__ __forceinline__ void unpack2(unsigned long long d, float& lo, float& hi) {
    asm("mov.b64 {%0,%1}, %2;" : "=f"(lo), "=f"(hi) : "l"(d));
}
__device__ __forceinline__ uint32_t smem_u32(const void* p) {
    uint32_t a;
    asm("{ .reg .u64 t; cvta.to.shared.u64 t, %1; cvt.u32.u64 %0, t; }"
        : "=r"(a) : "l"(p));
    return a;
}

// ---------------------------------------------------------------------------
// Kernel 1: causal depthwise conv (K=4) + swish
// y[b,s,d] = swish( sum_k x[b, s+k-3, d] * ck[k,d] + cb[d] )
// ---------------------------------------------------------------------------
__global__ void conv_swish_kernel(const float* __restrict__ x,
                                  const float* __restrict__ ck,
                                  const float* __restrict__ cb) {
    size_t idx = (size_t)blockIdx.x * blockDim.x + threadIdx.x;
    size_t total = (size_t)BB * SS * DD;
    if (idx >= total) return;
    int d = idx & (DD - 1);
    size_t bs = idx >> 10;
    int s = (int)(bs & (SS - 1));
    size_t b = bs >> 11;
    float acc = cb[d];
    const float* xb = x + b * (size_t)SS * DD + d;
#pragma unroll
    for (int k = 0; k < 4; k++) {
        int ss = s + k - 3;
        if (ss >= 0) acc = fmaf(xb[(size_t)ss * DD], ck[k * DD + d], acc);
    }
    d_xconv[idx] = acc / (1.0f + expf(-acc)) * 1.0f == 0.0f ? 0.0f : acc / (1.0f + expf(-acc));
}

// NOTE: expression above risks precedence bugs; use clean version instead.
__global__ void conv_swish_kernel2(const float* __restrict__ x,
                                   const float* __restrict__ ck,
                                   const float* __restrict__ cb) {
    size_t idx = (size_t)blockIdx.x * blockDim.x + threadIdx.x;
    size_t total = (size_t)BB * SS * DD;
    if (idx >= total) return;
    int d = idx & (DD - 1);
    size_t bs = idx >> 10;
    int s = (int)(bs & (SS - 1));
    size_t b = bs >> 11;
    float acc = cb[d];
    const float* xb = x + b * (size_t)SS * DD + d;
#pragma unroll
    for (int k = 0; k < 4; k++) {
        int ss = s + k - 3;
        if (ss >= 0) acc = fmaf(xb[(size_t)ss * DD], ck[k * DD + d], acc);
    }
    float sig = 1.0f / (1.0f + expf(-acc));
    d_xconv[idx] = acc * sig;
}

// ---------------------------------------------------------------------------
// Kernel 2: gate GEMMs (fp32, f32x2 FMA), epilogue adds rec_bias.
// For head h, gate g: C = A_h @ W_g[h]  where A = xconv (g<2) or x (g>=2).
// Writes d_G[((b*NH+h)*S + s)*1024 + g*256 + e]
// ---------------------------------------------------------------------------
#define BM 64
#define BN 64
#define BK 16

__global__ __launch_bounds__(256)
void gemm_gates_kernel(const float* __restrict__ x,
                       const float* __restrict__ w_i, const float* __restrict__ w_f,
                       const float* __restrict__ w_z, const float* __restrict__ w_o,
                       const float* __restrict__ rec_bias) {
    __shared__ float As[BK][BM + 4];   // row stride 68 floats (16B-aligned rows)
    __shared__ float Bs[BK][BN + 8];   // row stride 72 floats (16B-aligned rows)

    int bx = blockIdx.x;
    int hg  = bx >> 9;           // 0..15
    int rem = bx & 511;
    int mt  = rem >> 2;          // 0..127
    int nt  = rem & 3;           // 0..3
    int h = hg >> 2, g = hg & 3;

    const float* A = (g < 2) ? d_xconv : x;
    const float* W = (g == 0) ? w_i : (g == 1) ? w_f : (g == 2) ? w_z : w_o;
    W += (size_t)h * DH * DH;
    int acol = h * DH;

    int tid = threadIdx.x;
    int a_m  = tid >> 2;               // 0..63
    int a_k4 = (tid & 3) << 2;         // 0,4,8,12
    int b_k  = tid >> 4;               // 0..15
    int b_n4 = (tid & 15) << 2;        // 0..60
    int ty = tid >> 4, tx = tid & 15;  // 16 x 16 threads, 4x4 micro-tile

    int m0 = mt * BM;
    const float* Aptr = A + (size_t)(m0 + a_m) * DD + acol + a_k4;
    const float* Wptr = W + (size_t)b_k * DH + nt * BN + b_n4;

    unsigned long long acc[4][2];
#pragma unroll
    for (int i = 0; i < 4; i++) { acc[i][0] = 0ULL; acc[i][1] = 0ULL; }

    for (int k0 = 0; k0 < DH; k0 += BK) {
        float4 av = *(const float4*)(Aptr + k0);
        float4 bv = *(const float4*)(Wptr + (size_t)k0 * DH);
        As[a_k4 + 0][a_m] = av.x;
        As[a_k4 + 1][a_m] = av.y;
        As[a_k4 + 2][a_m] = av.z;
        As[a_k4 + 3][a_m] = av.w;
        *(float4*)&Bs[b_k][b_n4] = bv;
        __syncthreads();
#pragma unroll
        for (int k = 0; k < BK; k++) {
            float4 a4 = *(const float4*)&As[k][ty * 4];
            float4 b4 = *(const float4*)&Bs[k][tx * 4];
            unsigned long long b01 = pack2(b4.x, b4.y);
            unsigned long long b23 = pack2(b4.z, b4.w);
            float ar[4] = {a4.x, a4.y, a4.z, a4.w};
#pragma unroll
            for (int i = 0; i < 4; i++) {
                unsigned long long ad = pack2(ar[i], ar[i]);
                acc[i][0] = fma2(ad, b01, acc[i][0]);
                acc[i][1] = fma2(ad, b23, acc[i][1]);
            }
        }
        __syncthreads();
    }

    int n = nt * BN + tx * 4;                     // e in 0..255
    const float* rb = rec_bias + (g * NH + h) * DH + n;
    float rb0 = rb[0], rb1 = rb[1], rb2 = rb[2], rb3 = rb[3];
#pragma unroll
    for (int i = 0; i < 4; i++) {
        int m = m0 + ty * 4 + i;
        int b = m >> 11;                // m / S
        int s = m & (SS - 1);
        float o0, o1, o2, o3;
        unpack2(acc[i][0], o0, o1);
        unpack2(acc[i][1], o2, o3);
        float4 outv = make_float4(o0 + rb0, o1 + rb1, o2 + rb2, o3 + rb3);
        size_t gidx = (((size_t)(b * NH + h) * SS + s) << 10) + g * DH + n;
        *(float4*)&d_G[gidx] = outv;
    }
}

// ---------------------------------------------------------------------------
// Kernel 3: the sequential sLSTM scan.
// One 8-CTA cluster per (b,h). CTA rank c owns outputs o in [c*128, c*128+128),
// o = g*256 + e. 512 threads: thread i -> o_local = i&127, sub = i>>7 (d-quarter).
// Weights held in registers (64 fp32/thread). Per step:
//   matvec -> smem partial reduce -> raw (double-buffered) -> cluster barrier
//   -> DSMEM gather of 4 gate raws -> redundant cell update in every CTA.
// ---------------------------------------------------------------------------
__global__ void __launch_bounds__(512, 1) __cluster_dims__(CLN, 1, 1)
scan_kernel(const float* __restrict__ rk) {
    __shared__ float y_s[DH];
    __shared__ float partial[4][128];
    __shared__ float rawbuf[2][128];

    int tid = threadIdx.x;
    int c   = blockIdx.x & (CLN - 1);       // cluster rank
    int cid = blockIdx.x >> 3;              // 0..15 = b*NH + h
    int h   = cid & (NH - 1);

    int o_local = tid & 127;
    int sub     = tid >> 7;                 // 0..3  (d-range quarter)
    int o  = c * 128 + o_local;
    int g  = o >> 8;
    int eo = o & 255;

    // ---- load this thread's 64 recurrent weights into registers ----
    float w[64];
    {
        const float* wp = rk + (((size_t)h * DH + sub * 64) * 4 + g) * DH + eo;
#pragma unroll
        for (int j = 0; j < 64; j++) w[j] = wp[(size_t)j * 4 * DH];
    }

    if (tid < DH) y_s[tid] = 0.0f;
    float c_st = 0.0f, n_st = 0.0f, m_st = 0.0f;

    const float* gbase = d_G + ((size_t)cid * SS) * (4 * DH) + c * 128;
    float* ysb = d_ys + (size_t)cid * SS * DH;

    float g_cur = (tid < 128) ? gbase[tid] : 0.0f;   // prefetch s=0

    uint32_t raw_base = smem_u32(&rawbuf[0][0]);

    __syncthreads();

    int par = 0;
    for (int s = 0; s < SS; s++) {
        // ---- matvec: partial over this thread's 64 d-values ----
        const float* yp = y_s + sub * 64;
        float a0 = 0.f, a1 = 0.f, a2 = 0.f, a3 = 0.f;
#pragma unroll
        for (int jj = 0; jj < 16; jj++) {
            float4 yv = *(const float4*)(yp + jj * 4);
            a0 = fmaf(yv.x, w[jj * 4 + 0], a0);
            a1 = fmaf(yv.y, w[jj * 4 + 1], a1);
            a2 = fmaf(yv.z, w[jj * 4 + 2], a2);
            a3 = fmaf(yv.w, w[jj * 4 + 3], a3);
        }
        partial[sub][o_local] = (a0 + a1) + (a2 + a3);
        __syncthreads();

        if (tid < 128) {
            float r = partial[0][tid] + partial[1][tid] +
                      partial[2][tid] + partial[3][tid] + g_cur;
            rawbuf[par][tid] = r;
        }
        // prefetch next step's gate values (long latency, consumed next iter)
        if (tid < 128 && s + 1 < SS)
            g_cur = gbase[(size_t)(s + 1) * (4 * DH) + tid];

        // ---- cluster barrier: publish raw, acquire peers' raw ----
        asm volatile("barrier.cluster.arrive.aligned;" ::: "memory");
        asm volatile("barrier.cluster.wait.aligned;"   ::: "memory");

        if (tid < DH) {
            int e = tid;
            float rv[4];
#pragma unroll
            for (int gg = 0; gg < 4; gg++) {
                uint32_t la = raw_base + (uint32_t)((par * 128 + (e & 127)) * 4);
                uint32_t peer = (uint32_t)(gg * 2 + (e >> 7));
                uint32_t pa;
                asm volatile("mapa.shared::cluster.u32 %0, %1, %2;"
                             : "=r"(pa) : "r"(la), "r"(peer));
                asm volatile("ld.shared::cluster.f32 %0, [%1];"
                             : "=f"(rv[gg]) : "r"(pa));
            }
            float ir = rv[0], fr = rv[1], zr = rv[2], orr = rv[3];
            // log_sigmoid(fr) = min(fr,0) - log1p(exp(-|fr|))
            float ls  = fminf(fr, 0.0f) - log1pf(expf(-fabsf(fr)));
            float lfm = m_st + ls;
            float mn  = fmaxf(ir, lfm);
            float ig  = expf(ir - mn);
            float fg  = expf(lfm - mn);
            c_st = fg * c_st + ig * tanhf(zr);
            n_st = fg * n_st + ig;
            m_st = mn;
            float sig = 1.0f / (1.0f + expf(-orr));
            float yv  = sig * (c_st / n_st);
            y_s[e] = yv;
            if (c == 0) ysb[(size_t)s * DH + e] = yv;
        }
        __syncthreads();
        par ^= 1;
    }
}

// ---------------------------------------------------------------------------
// Kernel 4: per-(b,h,s) GroupNorm over DH=256 + affine, write final output.
// ---------------------------------------------------------------------------
__global__ __launch_bounds__(256)
void groupnorm_kernel(const float* __restrict__ gn_scale,
                      const float* __restrict__ gn_bias,
                      float* __restrict__ out) {
    __shared__ float red_s[8];
    __shared__ float red_q[8];
    __shared__ float mu_sh, rs_sh;

    int row = blockIdx.x;              // cid*S + s
    int e   = threadIdx.x;
    int cid = row >> 11;
    int s   = row & (SS - 1);
    int b = cid >> 2, h = cid & 3;

    float v = d_ys[(size_t)row * DH + e];
    float sv = v, sq = v * v;
#pragma unroll
    for (int off = 16; off > 0; off >>= 1) {
        sv += __shfl_down_sync(0xFFFFFFFFu, sv, off);
        sq += __shfl_down_sync(0xFFFFFFFFu, sq, off);
    }
    int warp = e >> 5, lane = e & 31;
    if (lane == 0) { red_s[warp] = sv; red_q[warp] = sq; }
    __syncthreads();
    if (e == 0) {
        float ts = 0.f, tq = 0.f;
#pragma unroll
        for (int i = 0; i < 8; i++) { ts += red_s[i]; tq += red_q[i]; }
        float mu  = ts * (1.0f / DH);
        float var = tq * (1.0f / DH) - mu * mu;
        mu_sh = mu;
        rs_sh = rsqrtf(var + 1e-6f);
    }
    __syncthreads();
    int d = h * DH + e;
    float yn = (v - mu_sh) * rs_sh;
    out[((size_t)b * SS + s) * DD + d] = yn * gn_scale[d] + gn_bias[d];
}

// ---------------------------------------------------------------------------
// Launch
// Inputs (metadata order): x, conv_kernel, conv_bias, w_i, w_f, w_z, w_o,
//                          rec_kernel, rec_bias, gn_scale, gn_bias
// ---------------------------------------------------------------------------
extern "C" void kernel_launch(void* const* d_in, const int* in_sizes, int n_in,
                              void* d_out, int out_size) {
    const float* x        = (const float*)d_in[0];
    const float* convk    = (const float*)d_in[1];
    const float* convb    = (const float*)d_in[2];
    const float* w_i      = (const float*)d_in[3];
    const float* w_f      = (const float*)d_in[4];
    const float* w_z      = (const float*)d_in[5];
    const float* w_o      = (const float*)d_in[6];
    const float* rec_k    = (const float*)d_in[7];
    const float* rec_b    = (const float*)d_in[8];
    const float* gn_scale = (const float*)d_in[9];
    const float* gn_bias  = (const float*)d_in[10];
    float* out = (float*)d_out;

    size_t total = (size_t)BB * SS * DD;
    conv_swish_kernel2<<<(unsigned)((total + 255) / 256), 256>>>(x, convk, convb);

    gemm_gates_kernel<<<16 * 128 * 4, 256>>>(x, w_i, w_f, w_z, w_o, rec_b);

    scan_kernel<<<NSEQ * CLN, 512>>>(rec_k);

    groupnorm_kernel<<<BB * NH * SS, 256>>>(gn_scale, gn_bias, out);
}